// round 1
// baseline (speedup 1.0000x reference)
#include <cuda_runtime.h>

// Problem constants
#define Bb 2
#define Nn 1024
#define Ee 8192
#define Dd 64
#define NT 16            // 16 tiles of 64 along N
#define PAIRS 136        // NT*(NT+1)/2 upper-triangular tile pairs
#define BK 32

// Device scratch (no allocation allowed in kernel_launch)
__device__ float g_scale[Bb * Ee];
__device__ float g_hw[Bb * Nn * Dd];
__device__ float g_adjA[(size_t)Bb * Nn * Nn];

// ---------------------------------------------------------------------------
// scale[b,e] = dot(H_e[b,e,:], p)
// ---------------------------------------------------------------------------
__global__ void scale_kernel(const float* __restrict__ H_e,
                             const float* __restrict__ p) {
    __shared__ float ps[64];
    if (threadIdx.x < 64) ps[threadIdx.x] = p[threadIdx.x];
    __syncthreads();
    int r = blockIdx.x * blockDim.x + threadIdx.x;
    if (r < Bb * Ee) {
        const float4* he = reinterpret_cast<const float4*>(H_e + (size_t)r * 64);
        float s = 0.f;
#pragma unroll
        for (int i = 0; i < 16; i++) {
            float4 v = he[i];
            s += v.x * ps[i * 4 + 0] + v.y * ps[i * 4 + 1] +
                 v.z * ps[i * 4 + 2] + v.w * ps[i * 4 + 3];
        }
        g_scale[r] = s;
    }
}

// ---------------------------------------------------------------------------
// HW[r,d] = dot(H_v[r,:], W[:,d])   (r over B*N)
// block (64,4): tx=d, 4 rows per block-y step; grid 512
// ---------------------------------------------------------------------------
__global__ void hw_kernel(const float* __restrict__ H_v,
                          const float* __restrict__ W) {
    __shared__ float ws[64 * 64];
    __shared__ float hv[4][64];
    int tx = threadIdx.x, ty = threadIdx.y;
    int tid = ty * 64 + tx;
    for (int i = tid; i < 64 * 64; i += 256) ws[i] = W[i];
    int row0 = blockIdx.x * 4;
    hv[ty][tx] = H_v[(size_t)(row0 + ty) * 64 + tx];
    __syncthreads();
    float acc = 0.f;
#pragma unroll
    for (int k = 0; k < 64; k++) acc += hv[ty][k] * ws[k * 64 + tx];
    g_hw[(size_t)(row0 + ty) * 64 + tx] = acc;
}

// ---------------------------------------------------------------------------
// multiplier1 = T * diag(scale) * T^T  (symmetric), fused with
// diag->1 and elementwise * adj_v. Writes adjA[n,m] and adjA[m,n].
// 64x64 tile per CTA, BK=32, TM=TN=4, 256 threads, 2 CTAs/SM.
// ---------------------------------------------------------------------------
__global__ void __launch_bounds__(256, 2)
mult_kernel(const float* __restrict__ T, const float* __restrict__ adj_v) {
    int b = blockIdx.x / PAIRS;
    int t = blockIdx.x % PAIRS;
    int ti = 0, rem = t;
    while (rem >= NT - ti) { rem -= NT - ti; ti++; }
    int tj = ti + rem;

    __shared__ float As[BK][68];   // [k][n-row], padded
    __shared__ float Bs[BK][68];   // [k][m-row], padded

    int tid = threadIdx.x;
    int tx = tid % 16;             // m micro-tile
    int ty = tid / 16;             // n micro-tile

    const float* Tb = T + (size_t)b * Nn * Ee;
    const float* sc = g_scale + b * Ee;

    float acc[4][4] = {};
    int lrow = tid / 8;            // 0..31 (loader row)
    int c4   = tid % 8;            // float4 column group in BK=32

    for (int k0 = 0; k0 < Ee; k0 += BK) {
        float4 s4 = *reinterpret_cast<const float4*>(sc + k0 + c4 * 4);
#pragma unroll
        for (int it = 0; it < 2; it++) {
            int row = lrow + it * 32;
            float4 a = *reinterpret_cast<const float4*>(
                Tb + (size_t)(ti * 64 + row) * Ee + k0 + c4 * 4);
            As[c4 * 4 + 0][row] = a.x * s4.x;
            As[c4 * 4 + 1][row] = a.y * s4.y;
            As[c4 * 4 + 2][row] = a.z * s4.z;
            As[c4 * 4 + 3][row] = a.w * s4.w;
            float4 bv = *reinterpret_cast<const float4*>(
                Tb + (size_t)(tj * 64 + row) * Ee + k0 + c4 * 4);
            Bs[c4 * 4 + 0][row] = bv.x;
            Bs[c4 * 4 + 1][row] = bv.y;
            Bs[c4 * 4 + 2][row] = bv.z;
            Bs[c4 * 4 + 3][row] = bv.w;
        }
        __syncthreads();
#pragma unroll
        for (int k = 0; k < BK; k++) {
            float4 a  = *reinterpret_cast<float4*>(&As[k][ty * 4]);
            float4 bq = *reinterpret_cast<float4*>(&Bs[k][tx * 4]);
            acc[0][0] += a.x * bq.x; acc[0][1] += a.x * bq.y;
            acc[0][2] += a.x * bq.z; acc[0][3] += a.x * bq.w;
            acc[1][0] += a.y * bq.x; acc[1][1] += a.y * bq.y;
            acc[1][2] += a.y * bq.z; acc[1][3] += a.y * bq.w;
            acc[2][0] += a.z * bq.x; acc[2][1] += a.z * bq.y;
            acc[2][2] += a.z * bq.z; acc[2][3] += a.z * bq.w;
            acc[3][0] += a.w * bq.x; acc[3][1] += a.w * bq.y;
            acc[3][2] += a.w * bq.z; acc[3][3] += a.w * bq.w;
        }
        __syncthreads();
    }

    const float* av = adj_v + (size_t)b * Nn * Nn;
    float* oA = g_adjA + (size_t)b * Nn * Nn;
#pragma unroll
    for (int i = 0; i < 4; i++) {
        int n = ti * 64 + ty * 4 + i;
#pragma unroll
        for (int j = 0; j < 4; j++) {
            int m = tj * 64 + tx * 4 + j;
            float mult = (n == m) ? 1.0f : acc[i][j];
            oA[(size_t)n * Nn + m] = mult * av[(size_t)n * Nn + m];
            if (ti != tj)
                oA[(size_t)m * Nn + n] = mult * av[(size_t)m * Nn + n];
        }
    }
}

// ---------------------------------------------------------------------------
// out[b,n,d] = sum_m adjA[b,n,m] * HW[b,m,d] + bias[d]
// block (64,4): each block computes 16 rows x 64 cols, K=1024; grid 128
// ---------------------------------------------------------------------------
__global__ void out_kernel(const float* __restrict__ bias,
                           float* __restrict__ out) {
    __shared__ float hws[64][64];
    __shared__ float aas[16][65];
    int tx = threadIdx.x, ty = threadIdx.y;
    int r0 = blockIdx.x * 16;        // global row over B*N (16 | 1024 so one batch)
    int b = r0 / Nn;
    int nloc0 = r0 % Nn;
    const float* AA  = g_adjA + (size_t)b * Nn * Nn;
    const float* HWb = g_hw + (size_t)b * Nn * Dd;
    float acc[4] = {0.f, 0.f, 0.f, 0.f};

    for (int k0 = 0; k0 < Nn; k0 += 64) {
#pragma unroll
        for (int i = 0; i < 16; i++)
            hws[ty + i * 4][tx] = HWb[(size_t)(k0 + ty + i * 4) * 64 + tx];
#pragma unroll
        for (int i = 0; i < 4; i++)
            aas[ty + i * 4][tx] = AA[(size_t)(nloc0 + ty + i * 4) * Nn + k0 + tx];
        __syncthreads();
#pragma unroll
        for (int kk = 0; kk < 64; kk++) {
            float h = hws[kk][tx];
#pragma unroll
            for (int rr = 0; rr < 4; rr++)
                acc[rr] += aas[ty + rr * 4][kk] * h;
        }
        __syncthreads();
    }
    float bb = bias[tx];
#pragma unroll
    for (int rr = 0; rr < 4; rr++)
        out[(size_t)(r0 + ty + rr * 4) * 64 + tx] = acc[rr] + bb;
}

// ---------------------------------------------------------------------------
extern "C" void kernel_launch(void* const* d_in, const int* in_sizes, int n_in,
                              void* d_out, int out_size) {
    const float* H_v   = (const float*)d_in[0];
    const float* H_e   = (const float*)d_in[1];
    // d_in[2] = adj_e : UNUSED by the reference math (512 MB we never touch)
    const float* adj_v = (const float*)d_in[3];
    const float* T     = (const float*)d_in[4];
    const float* W     = (const float*)d_in[5];
    const float* p     = (const float*)d_in[6];
    const float* bias  = (const float*)d_in[7];
    float* out = (float*)d_out;

    scale_kernel<<<(Bb * Ee + 255) / 256, 256>>>(H_e, p);
    hw_kernel<<<(Bb * Nn) / 4, dim3(64, 4)>>>(H_v, W);
    mult_kernel<<<Bb * PAIRS, 256>>>(T, adj_v);
    out_kernel<<<(Bb * Nn) / 16, dim3(64, 4)>>>(bias, out);

    // Second tuple output: H_e pass-through, appended after `output`
    const long long out_elems  = (long long)Bb * Nn * Dd;        // 131072
    const long long he_elems   = (long long)Bb * Ee * 64;        // 1048576
    if ((long long)out_size >= out_elems + he_elems) {
        cudaMemcpyAsync(out + out_elems, H_e,
                        (size_t)he_elems * sizeof(float),
                        cudaMemcpyDeviceToDevice, 0);
    }
}

// round 3
// speedup vs baseline: 2.6071x; 2.6071x over previous
#include <cuda_runtime.h>
#include <cuda_bf16.h>
#include <cstdint>

// Problem constants
#define Bb 2
#define Nn 1024
#define Ee 8192
#define Dd 64
#define NT8 8            // 8 tiles of 128 along N
#define PAIRS8 36        // upper-triangular tile pairs
#define KC 64            // K elements per stage (bf16 -> 128B rows, SW128)
#define KSPLIT 2
#define KHALF (Ee / KSPLIT)        // 4096
#define NCHUNK (KHALF / KC)        // 64

// ---------------------------------------------------------------------------
// Device scratch
// ---------------------------------------------------------------------------
__device__ float g_scale[Bb * Ee];
__device__ float g_hw[Bb * Nn * Dd];
__device__ float g_adjA[(size_t)Bb * Nn * Nn];
__device__ float g_outp[4][Bb * Nn * Dd];
__device__ float g_part[(size_t)Bb * PAIRS8 * KSPLIT * 128 * 128];
__device__ __nv_bfloat16 g_Ahi[(size_t)Bb * Nn * Ee];
__device__ __nv_bfloat16 g_Alo[(size_t)Bb * Nn * Ee];
__device__ __nv_bfloat16 g_Bhi[(size_t)Bb * Nn * Ee];
__device__ __nv_bfloat16 g_Blo[(size_t)Bb * Nn * Ee];

// ---------------------------------------------------------------------------
// Portable PTX helpers (sm_80-class only: cp.async, ldmatrix, mma.sync)
// ---------------------------------------------------------------------------
__device__ __forceinline__ uint32_t smem_u32(const void* p) {
    uint32_t a;
    asm("{ .reg .u64 t; cvta.to.shared.u64 t, %1; cvt.u32.u64 %0, t; }" : "=r"(a) : "l"(p));
    return a;
}
#define CP16(dst, src) \
    asm volatile("cp.async.cg.shared.global [%0], [%1], 16;" :: "r"(dst), "l"(src))
#define CP_COMMIT() asm volatile("cp.async.commit_group;")
#define CP_WAIT0()  asm volatile("cp.async.wait_group 0;")
#define CP_WAIT1()  asm volatile("cp.async.wait_group 1;")
#define SWZ(x) ((x) ^ (((x) >> 3) & 0x70))

__device__ __forceinline__ void ldsm4(uint32_t* r, uint32_t addr) {
    asm volatile("ldmatrix.sync.aligned.m8n8.x4.shared.b16 {%0,%1,%2,%3}, [%4];"
                 : "=r"(r[0]), "=r"(r[1]), "=r"(r[2]), "=r"(r[3]) : "r"(addr));
}
__device__ __forceinline__ void mma16816(float* c, const uint32_t* a, const uint32_t* b) {
    asm volatile(
        "mma.sync.aligned.m16n8k16.row.col.f32.bf16.bf16.f32 "
        "{%0,%1,%2,%3}, {%4,%5,%6,%7}, {%8,%9}, {%0,%1,%2,%3};"
        : "+f"(c[0]), "+f"(c[1]), "+f"(c[2]), "+f"(c[3])
        : "r"(a[0]), "r"(a[1]), "r"(a[2]), "r"(a[3]), "r"(b[0]), "r"(b[1]));
}

// ---------------------------------------------------------------------------
// scale[b,e] = dot(H_e[b,e,:], p)
// ---------------------------------------------------------------------------
__global__ void scale_kernel(const float* __restrict__ H_e,
                             const float* __restrict__ p) {
    __shared__ float ps[64];
    if (threadIdx.x < 64) ps[threadIdx.x] = p[threadIdx.x];
    __syncthreads();
    int r = blockIdx.x * blockDim.x + threadIdx.x;
    if (r < Bb * Ee) {
        const float4* he = reinterpret_cast<const float4*>(H_e + (size_t)r * 64);
        float s = 0.f;
#pragma unroll
        for (int i = 0; i < 16; i++) {
            float4 v = he[i];
            s += v.x * ps[i * 4 + 0] + v.y * ps[i * 4 + 1] +
                 v.z * ps[i * 4 + 2] + v.w * ps[i * 4 + 3];
        }
        g_scale[r] = s;
    }
}

// ---------------------------------------------------------------------------
// prep: split (T*scale) and T into bf16 hi/lo arrays
// ---------------------------------------------------------------------------
__global__ void prep_kernel(const float* __restrict__ T) {
    size_t idx8 = ((size_t)blockIdx.x * blockDim.x + threadIdx.x) * 8;
    if (idx8 >= (size_t)Bb * Nn * Ee) return;
    size_t row = idx8 >> 13;
    int e0 = (int)(idx8 & 8191);
    int b = (int)(row >> 10);
    const float4* tp = reinterpret_cast<const float4*>(T + idx8);
    float4 t0 = tp[0], t1 = tp[1];
    const float4* sp = reinterpret_cast<const float4*>(g_scale + b * Ee + e0);
    float4 s0 = sp[0], s1 = sp[1];
    float tv[8] = {t0.x, t0.y, t0.z, t0.w, t1.x, t1.y, t1.z, t1.w};
    float sv[8] = {s0.x, s0.y, s0.z, s0.w, s1.x, s1.y, s1.z, s1.w};
    __align__(16) __nv_bfloat16 ah[8], al[8], bh[8], bl[8];
#pragma unroll
    for (int i = 0; i < 8; i++) {
        float a = tv[i] * sv[i];
        ah[i] = __float2bfloat16_rn(a);
        al[i] = __float2bfloat16_rn(a - __bfloat162float(ah[i]));
        bh[i] = __float2bfloat16_rn(tv[i]);
        bl[i] = __float2bfloat16_rn(tv[i] - __bfloat162float(bh[i]));
    }
    *reinterpret_cast<uint4*>(g_Ahi + idx8) = *reinterpret_cast<uint4*>(ah);
    *reinterpret_cast<uint4*>(g_Alo + idx8) = *reinterpret_cast<uint4*>(al);
    *reinterpret_cast<uint4*>(g_Bhi + idx8) = *reinterpret_cast<uint4*>(bh);
    *reinterpret_cast<uint4*>(g_Blo + idx8) = *reinterpret_cast<uint4*>(bl);
}

// ---------------------------------------------------------------------------
// HW[r,d] = dot(H_v[r,:], W[:,d])
// ---------------------------------------------------------------------------
__global__ void hw_kernel(const float* __restrict__ H_v,
                          const float* __restrict__ W) {
    __shared__ float ws[64 * 64];
    __shared__ float hv[4][64];
    int tx = threadIdx.x, ty = threadIdx.y;
    int tid = ty * 64 + tx;
    for (int i = tid; i < 64 * 64; i += 256) ws[i] = W[i];
    int row0 = blockIdx.x * 4;
    hv[ty][tx] = H_v[(size_t)(row0 + ty) * 64 + tx];
    __syncthreads();
    float acc = 0.f;
#pragma unroll
    for (int k = 0; k < 64; k++) acc += hv[ty][k] * ws[k * 64 + tx];
    g_hw[(size_t)(row0 + ty) * 64 + tx] = acc;
}

// ---------------------------------------------------------------------------
// mult partial: 128x128 tile, half-K per CTA, bf16 3-split via mma.sync
// grid = Bb*PAIRS8*KSPLIT = 144, 256 threads (8 warps, warp grid 2x4)
// ---------------------------------------------------------------------------
#define OFF_AHI 0
#define OFF_ALO 16384
#define OFF_BHI 32768
#define OFF_BLO 49152
#define STAGE_BYTES 65536
#define MULT_SMEM (3 * STAGE_BYTES)

__global__ void __launch_bounds__(256, 1)
mult_partial(const float* __restrict__ dummy) {
    extern __shared__ __align__(1024) char smraw[];
    uint32_t stg = smem_u32(smraw);

    int tid = threadIdx.x;
    int wid = tid >> 5;
    int lid = tid & 31;
    int wm = wid & 1;          // m-half (64 rows)
    int wn = wid >> 1;         // n-quarter (32 cols)

    int p2 = blockIdx.x;
    int pair = p2 >> 1;
    int ksp = p2 & 1;
    int b = pair / PAIRS8;
    int t = pair % PAIRS8;
    int ti = 0, rem = t;
    while (rem >= NT8 - ti) { rem -= NT8 - ti; ti++; }
    int tj = ti + rem;

    size_t rowA = (size_t)(b * Nn + ti * 128);
    size_t rowB = (size_t)(b * Nn + tj * 128);
    int kbase = ksp * KHALF;

    // stage loader: 16 x cp.async(16B) per thread
    auto load_stage = [&](int sidx, int k0) {
        uint32_t sb = stg + sidx * STAGE_BYTES;
#pragma unroll
        for (int i = 0; i < 4; i++) {
            int chunk = tid + i * 256;          // 0..1023
            int row = chunk >> 3, cc = chunk & 7;
            uint32_t swo = SWZ((uint32_t)(row * 128 + cc * 16));
            size_t ga = (rowA + row) * (size_t)Ee + k0 + cc * 8;
            size_t gb = (rowB + row) * (size_t)Ee + k0 + cc * 8;
            CP16(sb + OFF_AHI + swo, g_Ahi + ga);
            CP16(sb + OFF_ALO + swo, g_Alo + ga);
            CP16(sb + OFF_BHI + swo, g_Bhi + gb);
            CP16(sb + OFF_BLO + swo, g_Blo + gb);
        }
        CP_COMMIT();
    };

    float acc[4][4][4];
#pragma unroll
    for (int i = 0; i < 4; i++)
#pragma unroll
        for (int j = 0; j < 4; j++)
#pragma unroll
            for (int q = 0; q < 4; q++) acc[i][j][q] = 0.f;

    load_stage(0, kbase);
    load_stage(1, kbase + KC);

    for (int s = 0; s < NCHUNK; s++) {
        if (s < NCHUNK - 1) CP_WAIT1(); else CP_WAIT0();
        __syncthreads();
        uint32_t sb = stg + (s % 3) * STAGE_BYTES;

#pragma unroll
        for (int ks = 0; ks < 4; ks++) {
            uint32_t ah[4][4], al[4][4], bh[2][4], bl[2][4];
            // A frags: row = wm*64 + mt*16 + (lid&15), kbyte = ks*32 + (lid>>4)*16
            uint32_t aoff = (uint32_t)((wm * 64 + (lid & 15)) * 128 +
                                       ks * 32 + ((lid >> 4) << 4));
#pragma unroll
            for (int mt = 0; mt < 4; mt++) {
                uint32_t so = SWZ(aoff + (uint32_t)(mt * 16 * 128));
                ldsm4(ah[mt], sb + OFF_AHI + so);
                ldsm4(al[mt], sb + OFF_ALO + so);
            }
            // B frags: row = wn*32 + nt2*16 + ((lid>>4)<<3) + (lid&7)
            //          kbyte = ks*32 + (((lid>>3)&1)<<4)
            uint32_t boff = (uint32_t)((wn * 32 + ((lid >> 4) << 3) + (lid & 7)) * 128 +
                                       ks * 32 + (((lid >> 3) & 1) << 4));
#pragma unroll
            for (int nt2 = 0; nt2 < 2; nt2++) {
                uint32_t so = SWZ(boff + (uint32_t)(nt2 * 16 * 128));
                ldsm4(bh[nt2], sb + OFF_BHI + so);
                ldsm4(bl[nt2], sb + OFF_BLO + so);
            }
            // 3 split terms: Ah*Bh + Ah*Bl + Al*Bh
#pragma unroll
            for (int mt = 0; mt < 4; mt++)
#pragma unroll
                for (int nt = 0; nt < 4; nt++) {
                    const uint32_t* bhp = &bh[nt >> 1][(nt & 1) * 2];
                    const uint32_t* blp = &bl[nt >> 1][(nt & 1) * 2];
                    mma16816(acc[mt][nt], ah[mt], bhp);
                    mma16816(acc[mt][nt], ah[mt], blp);
                    mma16816(acc[mt][nt], al[mt], bhp);
                }
        }
        if (s + 2 < NCHUNK) load_stage((s + 2) % 3, kbase + (s + 2) * KC);
    }

    // write partial tile
    float* pt = g_part + (size_t)p2 * 128 * 128;
#pragma unroll
    for (int mt = 0; mt < 4; mt++)
#pragma unroll
        for (int nt = 0; nt < 4; nt++) {
            int r = wm * 64 + mt * 16 + (lid >> 2);
            int c = wn * 32 + nt * 8 + (lid & 3) * 2;
            *reinterpret_cast<float2*>(pt + (size_t)r * 128 + c) =
                make_float2(acc[mt][nt][0], acc[mt][nt][1]);
            *reinterpret_cast<float2*>(pt + (size_t)(r + 8) * 128 + c) =
                make_float2(acc[mt][nt][2], acc[mt][nt][3]);
        }
}

// ---------------------------------------------------------------------------
// combine: M = part0+part1; diag->1; adjA = M*adj_v for (ti,tj) and (tj,ti)
// grid = Bb*PAIRS8 = 72, 256 threads, dynamic smem 128*129*4
// ---------------------------------------------------------------------------
__global__ void combine_kernel(const float* __restrict__ adj_v) {
    extern __shared__ float sm[];
    int p = blockIdx.x;
    int b = p / PAIRS8;
    int t = p % PAIRS8;
    int ti = 0, rem = t;
    while (rem >= NT8 - ti) { rem -= NT8 - ti; ti++; }
    int tj = ti + rem;

    const float* p0 = g_part + (size_t)(p * 2 + 0) * 16384;
    const float* p1 = g_part + (size_t)(p * 2 + 1) * 16384;
    const float* av = adj_v + (size_t)b * Nn * Nn;
    float* oA = g_adjA + (size_t)b * Nn * Nn;

    for (int idx = threadIdx.x; idx < 16384; idx += 256) {
        int r = idx >> 7, c = idx & 127;
        float m = p0[idx] + p1[idx];
        sm[r * 129 + c] = m;
        int n = ti * 128 + r, mm = tj * 128 + c;
        float v = (n == mm) ? 1.f : m;
        oA[(size_t)n * Nn + mm] = v * av[(size_t)n * Nn + mm];
    }
    if (ti != tj) {
        __syncthreads();
        for (int idx = threadIdx.x; idx < 16384; idx += 256) {
            int r2 = idx >> 7, c2 = idx & 127;
            float m = sm[c2 * 129 + r2];
            int n2 = tj * 128 + r2, m2 = ti * 128 + c2;
            oA[(size_t)n2 * Nn + m2] = m * av[(size_t)n2 * Nn + m2];
        }
    }
}

// ---------------------------------------------------------------------------
// out split-K: partial[ks] = adjA[:, ks*256:(ks+1)*256] @ HW[ks*256:...]
// ---------------------------------------------------------------------------
__global__ void out_stage(const float* dummy) {
    __shared__ float hws[64][64];
    __shared__ float aas[16][65];
    int tx = threadIdx.x, ty = threadIdx.y;
    int r0 = blockIdx.x * 16;
    int ks = blockIdx.y;
    int b = r0 / Nn;
    int nloc0 = r0 % Nn;
    int kbase = ks * 256;
    const float* AA = g_adjA + (size_t)b * Nn * Nn;
    const float* HWb = g_hw + (size_t)b * Nn * Dd;
    float acc[4] = {0.f, 0.f, 0.f, 0.f};

    for (int k0 = 0; k0 < 256; k0 += 64) {
#pragma unroll
        for (int i = 0; i < 16; i++)
            hws[ty + i * 4][tx] = HWb[(size_t)(kbase + k0 + ty + i * 4) * 64 + tx];
#pragma unroll
        for (int i = 0; i < 4; i++)
            aas[ty + i * 4][tx] = AA[(size_t)(nloc0 + ty + i * 4) * Nn + kbase + k0 + tx];
        __syncthreads();
#pragma unroll
        for (int kk = 0; kk < 64; kk++) {
            float h = hws[kk][tx];
#pragma unroll
            for (int rr = 0; rr < 4; rr++)
                acc[rr] += aas[ty + rr * 4][kk] * h;
        }
        __syncthreads();
    }
#pragma unroll
    for (int rr = 0; rr < 4; rr++)
        g_outp[ks][(size_t)(r0 + ty + rr * 4) * 64 + tx] = acc[rr];
}

__global__ void out_reduce(const float* __restrict__ bias, float* __restrict__ out) {
    int i = blockIdx.x * 256 + threadIdx.x;
    if (i < Bb * Nn * Dd)
        out[i] = g_outp[0][i] + g_outp[1][i] + g_outp[2][i] + g_outp[3][i] + bias[i & 63];
}

// ---------------------------------------------------------------------------
extern "C" void kernel_launch(void* const* d_in, const int* in_sizes, int n_in,
                              void* d_out, int out_size) {
    const float* H_v   = (const float*)d_in[0];
    const float* H_e   = (const float*)d_in[1];
    // d_in[2] = adj_e : unused by the reference math
    const float* adj_v = (const float*)d_in[3];
    const float* T     = (const float*)d_in[4];
    const float* W     = (const float*)d_in[5];
    const float* p     = (const float*)d_in[6];
    const float* bias  = (const float*)d_in[7];
    float* out = (float*)d_out;

    static bool attr_set = false;
    if (!attr_set) {
        cudaFuncSetAttribute(mult_partial, cudaFuncAttributeMaxDynamicSharedMemorySize,
                             MULT_SMEM);
        cudaFuncSetAttribute(combine_kernel, cudaFuncAttributeMaxDynamicSharedMemorySize,
                             128 * 129 * 4);
        attr_set = true;
    }

    scale_kernel<<<(Bb * Ee + 255) / 256, 256>>>(H_e, p);
    prep_kernel<<<(Bb * Nn * Ee / 8 + 255) / 256, 256>>>(T);
    hw_kernel<<<(Bb * Nn) / 4, dim3(64, 4)>>>(H_v, W);
    mult_partial<<<Bb * PAIRS8 * KSPLIT, 256, MULT_SMEM>>>(nullptr);
    combine_kernel<<<Bb * PAIRS8, 256, 128 * 129 * 4>>>(adj_v);
    out_stage<<<dim3((Bb * Nn) / 16, 4), dim3(64, 4)>>>(nullptr);
    out_reduce<<<(Bb * Nn * Dd + 255) / 256, 256>>>(bias, out);

    // Second tuple output: H_e pass-through, appended after `output`
    const long long out_elems = (long long)Bb * Nn * Dd;     // 131072
    const long long he_elems  = (long long)Bb * Ee * 64;     // 1048576
    if ((long long)out_size >= out_elems + he_elems) {
        cudaMemcpyAsync(out + out_elems, H_e,
                        (size_t)he_elems * sizeof(float),
                        cudaMemcpyDeviceToDevice, 0);
    }
}